// round 7
// baseline (speedup 1.0000x reference)
#include <cuda_runtime.h>

#define Tv 512
#define ROWW  60                 // raw floats per seq row (56 data + 4 pad) -> 240B
#define XROWW 70                 // expd u64 per lane row (8 steps x 8 + 6 pad) -> 560B
#define LROWW 20                 // ints per seq row: 8 lab + 8 msk + 4 pad
#define RAWF  (64 * ROWW)        // floats per raw stage
#define EXPDU (32 * XROWW)       // u64 per expd stage
#define LMEMI (64 * LROWW)       // ints per lmem stage
#define SMEM_BYTES (4*RAWF*4 + 2*EXPDU*8 + 3*LMEMI*4 + 49*4)

typedef unsigned long long u64;

static __device__ __forceinline__ u64 PK(float a, float b) {
    u64 r; asm("mov.b64 %0,{%1,%2};" : "=l"(r) : "r"(__float_as_uint(a)), "r"(__float_as_uint(b))); return r;
}
static __device__ __forceinline__ void UPK(u64 v, float& a, float& b) {
    unsigned x, y; asm("mov.b64 {%0,%1},%2;" : "=r"(x), "=r"(y) : "l"(v));
    a = __uint_as_float(x); b = __uint_as_float(y);
}
static __device__ __forceinline__ u64 FMA2(u64 a, u64 b, u64 c) {
    u64 d; asm("fma.rn.f32x2 %0,%1,%2,%3;" : "=l"(d) : "l"(a), "l"(b), "l"(c)); return d;
}
static __device__ __forceinline__ u64 MUL2(u64 a, u64 b) {
    u64 d; asm("mul.rn.f32x2 %0,%1,%2;" : "=l"(d) : "l"(a), "l"(b)); return d;
}
static __device__ __forceinline__ void cpa16(void* dst, const void* src) {
    unsigned d = (unsigned)__cvta_generic_to_shared(dst);
    asm volatile("cp.async.cg.shared.global [%0], [%1], 16;" :: "r"(d), "l"(src));
}
#define CP_COMMIT() asm volatile("cp.async.commit_group;")
#define CP_WAIT0()  asm volatile("cp.async.wait_group 0;")
#define CP_WAIT1()  asm volatile("cp.async.wait_group 1;")
#define CP_WAIT2()  asm volatile("cp.async.wait_group 2;")

__global__ void __launch_bounds__(128, 1)
crf_fwd_kernel(const float* __restrict__ em,
               const int* __restrict__ labels,
               const int* __restrict__ mask,
               const float* __restrict__ startT,
               const float* __restrict__ endT,
               const float* __restrict__ trans,
               float* __restrict__ out)
{
    extern __shared__ char sbase[];
    float* RAW  = (float*)sbase;                                    // 4 stages
    u64*   EXPD = (u64*)(sbase + 4*RAWF*4);                         // 2 stages
    int*   LMEM = (int*)(sbase + 4*RAWF*4 + 2*EXPDU*8);             // 3 stages
    float* STR  = (float*)(sbase + 4*RAWF*4 + 2*EXPDU*8 + 3*LMEMI*4);

    const int tid  = threadIdx.x;
    const int wid  = tid >> 5;
    const int lane = tid & 31;

    for (int i = tid; i < 49; i += 128) STR[i] = trans[i];

    const int base = blockIdx.x * 64;                 // 64 sequences per CTA
    const float* emb  = em + (size_t)base * (Tv * 7);
    const int*   labb = labels + (size_t)base * Tv;
    const int*   mskb = mask   + (size_t)base * Tv;

    // ---- role state ----
    u64 EE[7][7], SS[7];          // W0: exp(trans) pairs, exp(start) pairs
    u64 p[7]; int xsA = 0, xsB = 0;
    int prev0 = 0, prev1 = 0; float num0 = 0.f, num1 = 0.f;  // W3

    if (wid == 0) {
#pragma unroll
        for (int i = 0; i < 7; i++)
#pragma unroll
            for (int j = 0; j < 7; j++) {
                float e = __expf(__ldg(&trans[i * 7 + j]));
                EE[i][j] = PK(e, e);
            }
#pragma unroll
        for (int j = 0; j < 7; j++) { float e = __expf(__ldg(startT + j)); SS[j] = PK(e, e); }
    }

    // ---- staging helpers ----
#define STAGE_RAW(MM, HALF) do { \
    float* _d = RAW + ((MM) & 3) * RAWF; \
    _Pragma("unroll") \
    for (int i = 0; i < 14; i++) { \
        int idx = i * 32 + lane + (HALF) * 448; \
        int r = (idx * 4682) >> 16;  int c = idx - r * 14; \
        cpa16(_d + r * ROWW + c * 4, emb + (size_t)r * (Tv * 7) + (MM) * 56 + c * 4); \
    } } while (0)

#define STAGE_LAB(MM) do { \
    int* _d = LMEM + ((MM) % 3) * LMEMI; \
    _Pragma("unroll") \
    for (int i = 0; i < 8; i++) { \
        int idx = i * 32 + lane; int s = idx >> 2; int c = idx & 3; \
        const int* _s = (c < 2) ? (labb + (size_t)s * Tv + (MM) * 8 + (c & 1) * 4) \
                                : (mskb + (size_t)s * Tv + (MM) * 8 + (c & 1) * 4); \
        cpa16(_d + s * LROWW + c * 4, _s); \
    } } while (0)

#define CONVERT(MM, S0) do { \
    const float* _rA = RAW + ((MM) & 3) * RAWF + lane * ROWW; \
    const float* _rB = _rA + 32 * ROWW; \
    u64* _x = EXPD + ((MM) & 1) * EXPDU + lane * XROWW; \
    _Pragma("unroll") \
    for (int s = (S0); s < (S0) + 4; s++) { \
        _Pragma("unroll") \
        for (int j = 0; j < 7; j++) \
            _x[s * 8 + j] = PK(__expf(_rA[s * 7 + j]), __expf(_rB[s * 7 + j])); \
    } } while (0)

    // ---- W0 step kernels ----
    auto FSTEP = [&](const u64* xp) {            // mask known 1
        u64 q[7];
#pragma unroll
        for (int j = 0; j < 7; j++) q[j] = MUL2(p[0], EE[0][j]);
#pragma unroll
        for (int i = 1; i < 7; i++)
#pragma unroll
            for (int j = 0; j < 7; j++) q[j] = FMA2(p[i], EE[i][j], q[j]);
#pragma unroll
        for (int j = 0; j < 7; j++) p[j] = MUL2(q[j], xp[j]);
    };
    auto SSTEP = [&](const u64* xp, int MA, int MB) {   // general masked
        u64 q[7];
#pragma unroll
        for (int j = 0; j < 7; j++) q[j] = MUL2(p[0], EE[0][j]);
#pragma unroll
        for (int i = 1; i < 7; i++)
#pragma unroll
            for (int j = 0; j < 7; j++) q[j] = FMA2(p[i], EE[i][j], q[j]);
#pragma unroll
        for (int j = 0; j < 7; j++) q[j] = MUL2(q[j], xp[j]);
        unsigned mA32 = MA ? 0xFFFFFFFFu : 0u;
        unsigned mB32 = MB ? 0xFFFFFFFFu : 0u;
        u64 mm = ((u64)mB32 << 32) | mA32;
#pragma unroll
        for (int j = 0; j < 7; j++) p[j] = (q[j] & mm) | (p[j] & ~mm);
    };

#define RENORM() do { \
    float aA[7], aB[7]; \
    _Pragma("unroll") for (int j = 0; j < 7; j++) UPK(p[j], aA[j], aB[j]); \
    float mxA = aA[0], mxB = aB[0]; \
    _Pragma("unroll") for (int j = 1; j < 7; j++) { mxA = fmaxf(mxA, aA[j]); mxB = fmaxf(mxB, aB[j]); } \
    int exA = (__float_as_int(mxA) >> 23) & 0xFF; \
    int exB = (__float_as_int(mxB) >> 23) & 0xFF; \
    float invA = __int_as_float((254 - exA) << 23); \
    float invB = __int_as_float((254 - exB) << 23); \
    xsA += exA - 127; xsB += exB - 127; \
    u64 iv = PK(invA, invB); \
    _Pragma("unroll") for (int j = 0; j < 7; j++) p[j] = MUL2(p[j], iv); } while (0)

    // ---- prologue ----
    if (wid == 1 || wid == 2) {
        int half = wid - 1;
        STAGE_RAW(0, half); CP_COMMIT();
        STAGE_RAW(1, half); CP_COMMIT();
        STAGE_RAW(2, half); CP_COMMIT();
        CP_WAIT2();                         // raw0 complete
        CONVERT(0, half ? 4 : 0);           // expd0
    } else if (wid == 3) {
        STAGE_LAB(0); CP_COMMIT();
        STAGE_LAB(1); CP_COMMIT();
        CP_WAIT0();                         // lab0, lab1 complete
    }
    __syncthreads();

    // ---- main loop: one macro (8 steps) per iteration ----
#pragma unroll 1
    for (int m = 0; m < 64; m++) {
        if (wid == 0) {
            const u64* xr = EXPD + (m & 1) * EXPDU + (unsigned)lane * XROWW;
            const int* mpA = LMEM + (m % 3) * LMEMI + lane * LROWW;
            const int* mpB = mpA + 32 * LROWW;
            int4 ma0 = *(const int4*)(mpA + 8), ma1 = *(const int4*)(mpA + 12);
            int4 mb0 = *(const int4*)(mpB + 8), mb1 = *(const int4*)(mpB + 12);
            if (m == 0) {
                // init t=0: p ~ exp(start)*exp(em0), per-side normalize
                float aA[7], aB[7];
#pragma unroll
                for (int j = 0; j < 7; j++) { u64 q0 = MUL2(SS[j], xr[j]); UPK(q0, aA[j], aB[j]); }
                float mxA = aA[0], mxB = aB[0];
#pragma unroll
                for (int j = 1; j < 7; j++) { mxA = fmaxf(mxA, aA[j]); mxB = fmaxf(mxB, aB[j]); }
                int exA = (__float_as_int(mxA) >> 23) & 0xFF;
                int exB = (__float_as_int(mxB) >> 23) & 0xFF;
                float invA = __int_as_float((254 - exA) << 23);
                float invB = __int_as_float((254 - exB) << 23);
                xsA = exA - 127; xsB = exB - 127;
#pragma unroll
                for (int j = 0; j < 7; j++) p[j] = PK(aA[j] * invA, aB[j] * invB);
                SSTEP(xr + 8,  ma0.y, mb0.y);
                SSTEP(xr + 16, ma0.z, mb0.z);
                SSTEP(xr + 24, ma0.w, mb0.w);
                SSTEP(xr + 32, ma1.x, mb1.x);
                SSTEP(xr + 40, ma1.y, mb1.y);
                SSTEP(xr + 48, ma1.z, mb1.z);
                SSTEP(xr + 56, ma1.w, mb1.w);
                RENORM();
            } else {
                int allm = ma0.x & ma0.y & ma0.z & ma0.w & ma1.x & ma1.y & ma1.z & ma1.w
                         & mb0.x & mb0.y & mb0.z & mb0.w & mb1.x & mb1.y & mb1.z & mb1.w;
                if (allm) {
#pragma unroll
                    for (int s = 0; s < 8; s++) FSTEP(xr + s * 8);
                } else {
                    SSTEP(xr,      ma0.x, mb0.x); SSTEP(xr + 8,  ma0.y, mb0.y);
                    SSTEP(xr + 16, ma0.z, mb0.z); SSTEP(xr + 24, ma0.w, mb0.w);
                    SSTEP(xr + 32, ma1.x, mb1.x); SSTEP(xr + 40, ma1.y, mb1.y);
                    SSTEP(xr + 48, ma1.z, mb1.z); SSTEP(xr + 56, ma1.w, mb1.w);
                }
                RENORM();
            }
        } else if (wid == 3) {
            // numerator for macro m (raw + labels in smem)
            const float* rbase = RAW + (m & 3) * RAWF;
            const int*   lbase = LMEM + (m % 3) * LMEMI;
#pragma unroll
            for (int k = 0; k < 2; k++) {
                int seq = lane + k * 32;
                const int* lr = lbase + seq * LROWW;
                const float* rr = rbase + seq * ROWW;
                int pv = k ? prev1 : prev0;
                float nm = k ? num1 : num0;
#pragma unroll
                for (int s = 0; s < 8; s++) {
                    int L = lr[s], M = lr[8 + s];
                    int Lc = L < 0 ? 0 : L;
                    if (m == 0 && s == 0) {
                        nm = __ldg(startT + Lc) + rr[Lc];
                        pv = Lc;
                    } else {
                        float v = STR[pv * 7 + Lc] + rr[s * 7 + Lc];
                        nm += M ? v : 0.f;
                        pv  = M ? Lc : pv;
                    }
                }
                if (k) { prev1 = pv; num1 = nm; } else { prev0 = pv; num0 = nm; }
            }
            if (m + 2 < 64) STAGE_LAB(m + 2);
            CP_COMMIT();
            CP_WAIT1();                       // lab[m+1] complete
        } else {
            int half = wid - 1;
            if (m + 3 < 64) STAGE_RAW(m + 3, half);
            CP_COMMIT();
            if (m + 1 < 64) {
                CP_WAIT2();                   // raw[m+1] complete
                CONVERT(m + 1, half ? 4 : 0); // expd[(m+1)&1]
            }
        }
        __syncthreads();
    }

    // ---- epilogues ----
    if (wid == 0) {
        float aA[7], aB[7];
#pragma unroll
        for (int j = 0; j < 7; j++) UPK(p[j], aA[j], aB[j]);
        float accA = 0.f, accB = 0.f;
#pragma unroll
        for (int j = 0; j < 7; j++) {
            float ee = __expf(__ldg(endT + j));
            accA = fmaf(aA[j], ee, accA);
            accB = fmaf(aB[j], ee, accB);
        }
        const float LN2 = 0.69314718055994531f;
        float r = (__logf(accA) + (float)xsA * LN2) + (__logf(accB) + (float)xsB * LN2);
#pragma unroll
        for (int off = 16; off > 0; off >>= 1)
            r += __shfl_xor_sync(0xFFFFFFFFu, r, off);
        if (lane == 0) atomicAdd(out, r);
    } else if (wid == 3) {
        num0 += __ldg(endT + prev0);
        num1 += __ldg(endT + prev1);
        float r = num0 + num1;
#pragma unroll
        for (int off = 16; off > 0; off >>= 1)
            r += __shfl_xor_sync(0xFFFFFFFFu, r, off);
        if (lane == 0) atomicAdd(out, -r);
    }

#undef STAGE_RAW
#undef STAGE_LAB
#undef CONVERT
#undef RENORM
}

extern "C" void kernel_launch(void* const* d_in, const int* in_sizes, int n_in,
                              void* d_out, int out_size)
{
    const float* em     = (const float*)d_in[0];
    const int*   labels = (const int*)  d_in[1];
    const int*   mask   = (const int*)  d_in[2];
    const float* startT = (const float*)d_in[3];
    const float* endT   = (const float*)d_in[4];
    const float* trans  = (const float*)d_in[5];

    cudaFuncSetAttribute(crf_fwd_kernel, cudaFuncAttributeMaxDynamicSharedMemorySize, SMEM_BYTES);
    cudaMemsetAsync(d_out, 0, sizeof(float));
    crf_fwd_kernel<<<128, 128, SMEM_BYTES>>>(em, labels, mask, startT, endT, trans, (float*)d_out);
}